// round 1
// baseline (speedup 1.0000x reference)
#include <cuda_runtime.h>
#include <cuda_bf16.h>

// ConnectedWithinCutoff: B=64 graphs, n=512 nodes each.
// Output (float32, concatenated in reference return order):
//   [0, B*n*n*2)                 edge_index_all as floats (src,dst interleaved)
//   [B*n*n*2, B*n*n*3)           edge_mask as 0.0/1.0
//   [B*n*n*3, B*n*n*3 + B)       num_edges per graph
//   [B*n*n*3 + B, ... + B*n*n)   distances [B,n,n]
//
// Store-bandwidth-bound: ~268 MB of stores per launch.

#define CUTOFF_F 5.0f
#define MAX_N 512
#define I_TILE 8
#define BLOCK_THREADS 256

__global__ void cwc_zero_numedges(float* ne, int B) {
    int i = blockIdx.x * blockDim.x + threadIdx.x;
    if (i < B) ne[i] = 0.0f;
}

__global__ __launch_bounds__(BLOCK_THREADS)
void cwc_main(const float* __restrict__ pos,
              float* __restrict__ out,
              int B, int n, int tilesPerGraph)
{
    __shared__ float sx[MAX_N];
    __shared__ float sy[MAX_N];
    __shared__ float sz[MAX_N];

    const int b  = blockIdx.x / tilesPerGraph;
    const int i0 = (blockIdx.x % tilesPerGraph) * I_TILE;
    const int tid = threadIdx.x;

    // Stage this graph's positions into shared (SoA, conflict-free).
    const float* gp = pos + (size_t)b * n * 3;
    for (int idx = tid; idx < n; idx += BLOCK_THREADS) {
        sx[idx] = gp[idx * 3 + 0];
        sy[idx] = gp[idx * 3 + 1];
        sz[idx] = gp[idx * 3 + 2];
    }
    __syncthreads();

    const int tx = tid & 127;   // j-group: covers j = tx*4 .. tx*4+3
    const int ty = tid >> 7;    // row phase (0 or 1)
    const int j  = tx * 4;

    const size_t nn       = (size_t)n * n;
    const size_t maskBase = (size_t)B * nn * 2;
    const size_t neBase   = maskBase + (size_t)B * nn;
    const size_t distBase = neBase + (size_t)B;

    const float fb = (float)(b * n);
    int cnt = 0;

    if (j < n) {
        #pragma unroll
        for (int r = ty; r < I_TILE; r += 2) {
            const int i = i0 + r;
            if (i >= n) break;
            const float xi = sx[i], yi = sy[i], zi = sz[i];

            float d0, d1, d2, d3;
            float m0, m1, m2, m3;
            {
                float dx, dy, dz;
                dx = xi - sx[j+0]; dy = yi - sy[j+0]; dz = zi - sz[j+0];
                d0 = sqrtf(dx*dx + dy*dy + dz*dz);
                m0 = (d0 <= CUTOFF_F && (j+0) != i) ? 1.0f : 0.0f;
                dx = xi - sx[j+1]; dy = yi - sy[j+1]; dz = zi - sz[j+1];
                d1 = sqrtf(dx*dx + dy*dy + dz*dz);
                m1 = (d1 <= CUTOFF_F && (j+1) != i) ? 1.0f : 0.0f;
                dx = xi - sx[j+2]; dy = yi - sy[j+2]; dz = zi - sz[j+2];
                d2 = sqrtf(dx*dx + dy*dy + dz*dz);
                m2 = (d2 <= CUTOFF_F && (j+2) != i) ? 1.0f : 0.0f;
                dx = xi - sx[j+3]; dy = yi - sy[j+3]; dz = zi - sz[j+3];
                d3 = sqrtf(dx*dx + dy*dy + dz*dz);
                m3 = (d3 <= CUTOFF_F && (j+3) != i) ? 1.0f : 0.0f;
            }
            cnt += (int)m0 + (int)m1 + (int)m2 + (int)m3;

            const size_t rowBase = (size_t)b * nn + (size_t)i * n + (size_t)j;

            // distances
            *reinterpret_cast<float4*>(out + distBase + rowBase) =
                make_float4(d0, d1, d2, d3);
            // mask
            *reinterpret_cast<float4*>(out + maskBase + rowBase) =
                make_float4(m0, m1, m2, m3);
            // edge_index pairs: (src, dst) per cell, src = b*n+i, dst = b*n+j+k
            const float src  = fb + (float)i;
            const float dstb = fb + (float)j;
            *reinterpret_cast<float4*>(out + rowBase * 2) =
                make_float4(src, dstb + 0.0f, src, dstb + 1.0f);
            *reinterpret_cast<float4*>(out + rowBase * 2 + 4) =
                make_float4(src, dstb + 2.0f, src, dstb + 3.0f);
        }
    }

    // num_edges: warp reduce, one float atomic per warp (counts are exact in fp32)
    #pragma unroll
    for (int off = 16; off > 0; off >>= 1)
        cnt += __shfl_down_sync(0xffffffffu, cnt, off);
    if ((tid & 31) == 0 && cnt > 0)
        atomicAdd(out + neBase + b, (float)cnt);
}

extern "C" void kernel_launch(void* const* d_in, const int* in_sizes, int n_in,
                              void* d_out, int out_size) {
    // inputs: [0] num_nodes int32 [B], [1] positions float32 [B*n, 3]
    const float* pos = (const float*)d_in[1];
    float* out = (float*)d_out;

    const int B = in_sizes[0];
    const int n = in_sizes[1] / (3 * B);

    const size_t nn = (size_t)n * n;
    const size_t neBase = (size_t)B * nn * 3;

    // zero num_edges slots (d_out is poisoned)
    cwc_zero_numedges<<<(B + 63) / 64, 64>>>(out + neBase, B);

    const int tilesPerGraph = (n + I_TILE - 1) / I_TILE;
    const int grid = B * tilesPerGraph;
    cwc_main<<<grid, BLOCK_THREADS>>>(pos, out, B, n, tilesPerGraph);
}

// round 2
// speedup vs baseline: 1.0723x; 1.0723x over previous
#include <cuda_runtime.h>
#include <cuda_bf16.h>

// ConnectedWithinCutoff: B=64 graphs, n=512 nodes each.
// Output (float32, concatenated in reference return order):
//   [0, B*n*n*2)                 edge_index_all as floats (src,dst interleaved)
//   [B*n*n*2, B*n*n*3)           edge_mask as 0.0/1.0
//   [B*n*n*3, B*n*n*3 + B)       num_edges per graph
//   [B*n*n*3 + B, ... + B*n*n)   distances [B,n,n]
//
// Store-bandwidth/concurrency-bound: ~268 MB of stores per launch.

#define CUTOFF_F 5.0f
#define MAX_N 512
#define I_TILE 8
#define BLOCK_THREADS 256
#define MAX_B 1024

// Self-resetting per-graph reduction state (zero-initialized at module load;
// the last-arriving block resets them to zero each launch, so every graph
// replay starts from a clean state).
__device__ int g_sum[MAX_B];
__device__ int g_arrived[MAX_B];

__global__ __launch_bounds__(BLOCK_THREADS, 6)
void cwc_main(const float* __restrict__ pos,
              float* __restrict__ out,
              int B, int n, int tilesPerGraph)
{
    __shared__ float sx[MAX_N];
    __shared__ float sy[MAX_N];
    __shared__ float sz[MAX_N];
    __shared__ int sCnt;

    const int b  = blockIdx.x / tilesPerGraph;
    const int i0 = (blockIdx.x % tilesPerGraph) * I_TILE;
    const int tid = threadIdx.x;

    if (tid == 0) sCnt = 0;

    // Stage this graph's positions into shared (SoA, conflict-free).
    const float* gp = pos + (size_t)b * n * 3;
    for (int idx = tid; idx < n; idx += BLOCK_THREADS) {
        sx[idx] = gp[idx * 3 + 0];
        sy[idx] = gp[idx * 3 + 1];
        sz[idx] = gp[idx * 3 + 2];
    }
    __syncthreads();

    const int tx = tid & 127;   // j-group: covers j = tx*4 .. tx*4+3
    const int ty = tid >> 7;    // row phase (0 or 1)
    const int j  = tx * 4;

    const size_t nn       = (size_t)n * n;
    const size_t maskBase = (size_t)B * nn * 2;
    const size_t neBase   = maskBase + (size_t)B * nn;
    const size_t distBase = neBase + (size_t)B;

    const float fb = (float)(b * n);
    int cnt = 0;

    if (j < n) {
        #pragma unroll
        for (int r = ty; r < I_TILE; r += 2) {
            const int i = i0 + r;
            if (i >= n) break;
            const float xi = sx[i], yi = sy[i], zi = sz[i];

            float d0, d1, d2, d3;
            float m0, m1, m2, m3;
            {
                float dx, dy, dz;
                dx = xi - sx[j+0]; dy = yi - sy[j+0]; dz = zi - sz[j+0];
                d0 = sqrtf(dx*dx + dy*dy + dz*dz);
                m0 = (d0 <= CUTOFF_F && (j+0) != i) ? 1.0f : 0.0f;
                dx = xi - sx[j+1]; dy = yi - sy[j+1]; dz = zi - sz[j+1];
                d1 = sqrtf(dx*dx + dy*dy + dz*dz);
                m1 = (d1 <= CUTOFF_F && (j+1) != i) ? 1.0f : 0.0f;
                dx = xi - sx[j+2]; dy = yi - sy[j+2]; dz = zi - sz[j+2];
                d2 = sqrtf(dx*dx + dy*dy + dz*dz);
                m2 = (d2 <= CUTOFF_F && (j+2) != i) ? 1.0f : 0.0f;
                dx = xi - sx[j+3]; dy = yi - sy[j+3]; dz = zi - sz[j+3];
                d3 = sqrtf(dx*dx + dy*dy + dz*dz);
                m3 = (d3 <= CUTOFF_F && (j+3) != i) ? 1.0f : 0.0f;
            }
            cnt += (int)m0 + (int)m1 + (int)m2 + (int)m3;

            const size_t rowBase = (size_t)b * nn + (size_t)i * n + (size_t)j;

            // streaming stores: write-once data, evict-first in L2
            __stcs(reinterpret_cast<float4*>(out + distBase + rowBase),
                   make_float4(d0, d1, d2, d3));
            __stcs(reinterpret_cast<float4*>(out + maskBase + rowBase),
                   make_float4(m0, m1, m2, m3));
            const float src  = fb + (float)i;
            const float dstb = fb + (float)j;
            __stcs(reinterpret_cast<float4*>(out + rowBase * 2),
                   make_float4(src, dstb + 0.0f, src, dstb + 1.0f));
            __stcs(reinterpret_cast<float4*>(out + rowBase * 2 + 4),
                   make_float4(src, dstb + 2.0f, src, dstb + 3.0f));
        }
    }

    // block-level edge count
    #pragma unroll
    for (int off = 16; off > 0; off >>= 1)
        cnt += __shfl_down_sync(0xffffffffu, cnt, off);
    if ((tid & 31) == 0 && cnt > 0)
        atomicAdd(&sCnt, cnt);
    __syncthreads();

    // last-arriving block per graph publishes num_edges and resets state
    if (tid == 0) {
        atomicAdd(&g_sum[b], sCnt);
        __threadfence();
        int old = atomicAdd(&g_arrived[b], 1);
        if (old == tilesPerGraph - 1) {
            int tot = atomicExch(&g_sum[b], 0);
            atomicExch(&g_arrived[b], 0);
            out[neBase + b] = (float)tot;
        }
    }
}

extern "C" void kernel_launch(void* const* d_in, const int* in_sizes, int n_in,
                              void* d_out, int out_size) {
    // inputs: [0] num_nodes int32 [B], [1] positions float32 [B*n, 3]
    const float* pos = (const float*)d_in[1];
    float* out = (float*)d_out;

    const int B = in_sizes[0];
    const int n = in_sizes[1] / (3 * B);

    const int tilesPerGraph = (n + I_TILE - 1) / I_TILE;
    const int grid = B * tilesPerGraph;
    cwc_main<<<grid, BLOCK_THREADS>>>(pos, out, B, n, tilesPerGraph);
}

// round 3
// speedup vs baseline: 1.0852x; 1.0121x over previous
#include <cuda_runtime.h>
#include <cuda_bf16.h>

// ConnectedWithinCutoff: B=64 graphs, n=512 nodes each.
// Output (float32, concatenated in reference return order):
//   [0, B*n*n*2)                 edge_index_all as floats (src,dst interleaved)
//   [B*n*n*2, B*n*n*3)           edge_mask as 0.0/1.0
//   [B*n*n*3, B*n*n*3 + B)       num_edges per graph
//   [B*n*n*3 + B, ... + B*n*n)   distances [B,n,n]
//
// ~268 MB of stores per launch; L1/LSU pipe is the observed limiter.

#define CUTOFF_F 5.0f
#define MAX_N 512
#define I_TILE 8
#define BLOCK_THREADS 256
#define MAX_B 1024

// Self-resetting per-graph reduction state (zero at module load; the last
// arriving block per graph resets it each launch → clean state every replay).
__device__ int g_sum[MAX_B];
__device__ int g_arrived[MAX_B];

__global__ __launch_bounds__(BLOCK_THREADS, 6)
void cwc_main(const float* __restrict__ pos,
              float* __restrict__ out,
              int B, int n, int tilesPerGraph)
{
    __shared__ __align__(16) float sx[MAX_N];
    __shared__ __align__(16) float sy[MAX_N];
    __shared__ __align__(16) float sz[MAX_N];
    __shared__ int sCnt;

    const int b  = blockIdx.x / tilesPerGraph;
    const int i0 = (blockIdx.x % tilesPerGraph) * I_TILE;
    const int tid = threadIdx.x;

    if (tid == 0) sCnt = 0;

    // Stage this graph's positions into shared (SoA).
    const float* gp = pos + (size_t)b * n * 3;
    for (int idx = tid; idx < n; idx += BLOCK_THREADS) {
        sx[idx] = gp[idx * 3 + 0];
        sy[idx] = gp[idx * 3 + 1];
        sz[idx] = gp[idx * 3 + 2];
    }
    __syncthreads();

    const int tx = tid & 127;   // j-group: covers j = tx*4 .. tx*4+3
    const int ty = tid >> 7;    // row phase (0 or 1)
    const int j  = tx * 4;

    const size_t nn       = (size_t)n * n;
    const size_t maskBase = (size_t)B * nn * 2;
    const size_t neBase   = maskBase + (size_t)B * nn;
    const size_t distBase = neBase + (size_t)B;

    const float fb = (float)(b * n);
    int cnt = 0;

    if (j < n) {
        // Hoist the 4 j-node positions into registers: 3x LDS.128, once.
        const float4 jx = *reinterpret_cast<const float4*>(&sx[j]);
        const float4 jy = *reinterpret_cast<const float4*>(&sy[j]);
        const float4 jz = *reinterpret_cast<const float4*>(&sz[j]);

        #pragma unroll
        for (int r = ty; r < I_TILE; r += 2) {
            const int i = i0 + r;
            if (i >= n) break;
            const float xi = sx[i], yi = sy[i], zi = sz[i];

            float dx, dy, dz;
            dx = xi - jx.x; dy = yi - jy.x; dz = zi - jz.x;
            const float d0 = sqrtf(dx*dx + dy*dy + dz*dz);
            dx = xi - jx.y; dy = yi - jy.y; dz = zi - jz.y;
            const float d1 = sqrtf(dx*dx + dy*dy + dz*dz);
            dx = xi - jx.z; dy = yi - jy.z; dz = zi - jz.z;
            const float d2 = sqrtf(dx*dx + dy*dy + dz*dz);
            dx = xi - jx.w; dy = yi - jy.w; dz = zi - jz.w;
            const float d3 = sqrtf(dx*dx + dy*dy + dz*dz);

            const float m0 = (d0 <= CUTOFF_F && (j+0) != i) ? 1.0f : 0.0f;
            const float m1 = (d1 <= CUTOFF_F && (j+1) != i) ? 1.0f : 0.0f;
            const float m2 = (d2 <= CUTOFF_F && (j+2) != i) ? 1.0f : 0.0f;
            const float m3 = (d3 <= CUTOFF_F && (j+3) != i) ? 1.0f : 0.0f;
            cnt += (int)m0 + (int)m1 + (int)m2 + (int)m3;

            const size_t rowBase = (size_t)b * nn + (size_t)i * n + (size_t)j;

            __stcs(reinterpret_cast<float4*>(out + distBase + rowBase),
                   make_float4(d0, d1, d2, d3));
            __stcs(reinterpret_cast<float4*>(out + maskBase + rowBase),
                   make_float4(m0, m1, m2, m3));
            const float src  = fb + (float)i;
            const float dstb = fb + (float)j;
            __stcs(reinterpret_cast<float4*>(out + rowBase * 2),
                   make_float4(src, dstb + 0.0f, src, dstb + 1.0f));
            __stcs(reinterpret_cast<float4*>(out + rowBase * 2 + 4),
                   make_float4(src, dstb + 2.0f, src, dstb + 3.0f));
        }
    }

    // block-level edge count
    #pragma unroll
    for (int off = 16; off > 0; off >>= 1)
        cnt += __shfl_down_sync(0xffffffffu, cnt, off);
    if ((tid & 31) == 0 && cnt > 0)
        atomicAdd(&sCnt, cnt);
    __syncthreads();

    // last-arriving block per graph publishes num_edges and resets state
    if (tid == 0) {
        atomicAdd(&g_sum[b], sCnt);
        __threadfence();
        int old = atomicAdd(&g_arrived[b], 1);
        if (old == tilesPerGraph - 1) {
            int tot = atomicExch(&g_sum[b], 0);
            atomicExch(&g_arrived[b], 0);
            out[neBase + b] = (float)tot;
        }
    }
}

extern "C" void kernel_launch(void* const* d_in, const int* in_sizes, int n_in,
                              void* d_out, int out_size) {
    // inputs: [0] num_nodes int32 [B], [1] positions float32 [B*n, 3]
    const float* pos = (const float*)d_in[1];
    float* out = (float*)d_out;

    const int B = in_sizes[0];
    const int n = in_sizes[1] / (3 * B);

    const int tilesPerGraph = (n + I_TILE - 1) / I_TILE;
    const int grid = B * tilesPerGraph;
    cwc_main<<<grid, BLOCK_THREADS>>>(pos, out, B, n, tilesPerGraph);
}